// round 14
// baseline (speedup 1.0000x reference)
#include <cuda_runtime.h>
#include <cuda_fp16.h>
#include <math.h>
#include <stdint.h>

#define D_MODEL 2048
#define NHEADS  16
#define DHEAD   128
#define SEQLEN  2048
#define BATCH   2
#define MROWS   (BATCH*SEQLEN)   // 4096
#define QK_SCALE 0.08838834764831845f   // 1/sqrt(128)
#define SPLIT_SC 2048.0f                // 2^11 scaled-correction factor
#define SPLIT_SCI (1.0f/2048.0f)

// ---------------- scratch (device globals; no allocation allowed) ----------------
__device__ float g_cos[SEQLEN*(DHEAD/2)];
__device__ float g_sin[SEQLEN*(DHEAD/2)];

// fp16 2-term.  A-side: single tensor (A1 = A0 * 2^-11 derived in registers).
// B-side: (value_f, (value - value_f)*2048).
__device__ __half g_xf[MROWS*D_MODEL];                // fp16(x)
__device__ __half g_wfh[4][D_MODEL*D_MODEL];          // 0=Wq 1=Wk 2=Wv 3=Wo : fp16(W)
__device__ __half g_wfl[4][D_MODEL*D_MODEL];          // fp16((W-hi)*2048)
__device__ __half g_qf[BATCH*NHEADS*SEQLEN*DHEAD];    // fp16(q·scale)   (A-side of QK^T)
__device__ __half g_kf[BATCH*NHEADS*SEQLEN*DHEAD];    // fp16(k)         (B-side of QK^T)
__device__ __half g_kr[BATCH*NHEADS*SEQLEN*DHEAD];    // fp16((k-kf)*2048)
__device__ __half g_vhf[BATCH*NHEADS*SEQLEN*DHEAD];   // fp16(v)         (B-side of PV)
__device__ __half g_vlf[BATCH*NHEADS*SEQLEN*DHEAD];   // fp16((v-vh)*2048)
__device__ __half g_af[MROWS*D_MODEL];                // fp16(attn out)  (A-side of out-proj)

// ---------------- PTX helpers (sm_80-level only) -----------------------------------
__device__ __forceinline__ uint32_t smem_u32(const void* p) {
    uint32_t a;
    asm("{ .reg .u64 t; cvta.to.shared.u64 t, %1; cvt.u32.u64 %0, t; }" : "=r"(a) : "l"(p));
    return a;
}
__device__ __forceinline__ void cp16(uint32_t dst, const void* src) {
    asm volatile("cp.async.cg.shared.global [%0], [%1], 16;" :: "r"(dst), "l"(src));
}
#define CP_COMMIT() asm volatile("cp.async.commit_group;" ::: "memory")
#define CP_WAIT(n)  asm volatile("cp.async.wait_group %0;" :: "n"(n) : "memory")

__device__ __forceinline__ void ldm_x4(uint32_t* r, uint32_t addr) {
    asm volatile("ldmatrix.sync.aligned.m8n8.x4.shared.b16 {%0,%1,%2,%3}, [%4];"
                 : "=r"(r[0]), "=r"(r[1]), "=r"(r[2]), "=r"(r[3]) : "r"(addr));
}
__device__ __forceinline__ void ldm_x4_t(uint32_t* r, uint32_t addr) {
    asm volatile("ldmatrix.sync.aligned.m8n8.x4.trans.shared.b16 {%0,%1,%2,%3}, [%4];"
                 : "=r"(r[0]), "=r"(r[1]), "=r"(r[2]), "=r"(r[3]) : "r"(addr));
}
__device__ __forceinline__ void mma_fp16(float* c, const uint32_t* a, uint32_t b0, uint32_t b1) {
    asm volatile("mma.sync.aligned.m16n8k16.row.col.f32.f16.f16.f32 "
                 "{%0,%1,%2,%3}, {%4,%5,%6,%7}, {%8,%9}, {%0,%1,%2,%3};"
                 : "+f"(c[0]), "+f"(c[1]), "+f"(c[2]), "+f"(c[3])
                 : "r"(a[0]), "r"(a[1]), "r"(a[2]), "r"(a[3]), "r"(b0), "r"(b1));
}
__device__ __forceinline__ uint32_t packh2(float lo, float hi) {   // fp16x2, first asm src -> upper
    uint32_t r;
    asm("cvt.rn.f16x2.f32 %0, %1, %2;" : "=r"(r) : "f"(hi), "f"(lo));
    return r;
}
__device__ __forceinline__ uint32_t h2scale(uint32_t v, uint32_t sc2) {  // fp16x2 * fp16x2
    uint32_t r;
    asm("mul.rn.f16x2 %0, %1, %2;" : "=r"(r) : "r"(v), "r"(sc2));
    return r;
}
#define SCI_H2 0x10001000u   // fp16x2 {2^-11, 2^-11}

// ---------------- RoPE tables ------------------------------------------------------
__global__ void rope_table_kernel() {
    int idx = blockIdx.x * blockDim.x + threadIdx.x;
    int pos = idx >> 6;
    int p   = idx & 63;
    double freq = exp(-((double)(2 * p) / 128.0) * log(10000.0));
    double ang  = (double)pos * freq;
    g_cos[idx] = (float)cos(ang);
    g_sin[idx] = (float)sin(ang);
}

// ---------------- split kernels ----------------------------------------------------
__global__ void split_x_kernel(const float* __restrict__ src) {
    int i = blockIdx.x * 256 + threadIdx.x;
    g_xf[i] = __float2half(src[i]);
}
__global__ void split_w_kernel(const float* __restrict__ w0, const float* __restrict__ w1,
                               const float* __restrict__ w2, const float* __restrict__ w3) {
    int i = blockIdx.x * 256 + threadIdx.x;
    int wsel = blockIdx.y;
    const float* s = (wsel == 0) ? w0 : (wsel == 1) ? w1 : (wsel == 2) ? w2 : w3;
    float v = s[i];
    __half h = __float2half(v);
    g_wfh[wsel][i] = h;
    g_wfl[wsel][i] = __float2half((v - __half2float(h)) * SPLIT_SC);
}

// ---------------- GEMM core: BM=BN=128, BK=16, 8 warps (2m x 4n), warp tile 64x32 ---
// 2-term fp16: acc = A*B0 + (A*2^-11)*B1.  8 LDSM per warp-stage for 16 MMAs.
#define GLD 24
#define T_A0 0
#define T_B0 (128*GLD)
#define T_B1 (2*128*GLD)
#define STAGE_HALVES (3*128*GLD)              // 9216 halves = 18432 B
#define SMEM_GEMM_BYTES (4*STAGE_HALVES*2)    // 73728 B

struct GemmCore {
    uint32_t sb;
    int lane, wm, wn, lrow, lc, lr, lh;
    const uint16_t *pA0, *pB0, *pB1;

    __device__ __forceinline__ void init(uint32_t sb_, int m0, int n0,
                                         const void* A0, const void* B0, const void* B1) {
        sb = sb_;
        int tid = threadIdx.x;
        lane = tid & 31;
        int warp = tid >> 5;
        wm = warp & 1; wn = warp >> 1;       // 2m x 4n, warp tile 64x32
        lrow = tid & 127; lc = tid >> 7;
        lr = lane & 15; lh = lane >> 4;
        pA0 = (const uint16_t*)A0 + (size_t)(m0 + lrow) * 2048;
        pB0 = (const uint16_t*)B0 + (size_t)(n0 + lrow) * 2048;
        pB1 = (const uint16_t*)B1 + (size_t)(n0 + lrow) * 2048;
    }
    __device__ __forceinline__ void load_stage(int s, int buf) {
        const int ks = s * 16 + lc * 8;
        const uint32_t base = sb + buf * STAGE_HALVES * 2;
        const uint32_t off = (lrow * GLD + lc * 8) * 2;
        cp16(base + T_A0*2 + off, pA0 + ks);
        cp16(base + T_B0*2 + off, pB0 + ks);
        cp16(base + T_B1*2 + off, pB1 + ks);
    }
    __device__ __forceinline__ void run(float acc[4][4][4]) {
        load_stage(0, 0); CP_COMMIT();
        load_stage(1, 1); CP_COMMIT();
        load_stage(2, 2); CP_COMMIT();
        for (int s = 0; s < 128; s++) {
            const int rem = 127 - s;
            if      (rem >= 2) CP_WAIT(2);
            else if (rem == 1) CP_WAIT(1);
            else               CP_WAIT(0);
            __syncthreads();
            const uint32_t base = sb + (s & 3) * STAGE_HALVES * 2;
            uint32_t a0[4][4], a1[4][4], b0[2][4], b1[2][4];
            #pragma unroll
            for (int mf = 0; mf < 4; mf++) {
                uint32_t ra = base + ((wm*64 + mf*16 + lr) * GLD + lh*8) * 2;
                ldm_x4(a0[mf], ra + T_A0*2);
                #pragma unroll
                for (int j = 0; j < 4; j++) a1[mf][j] = h2scale(a0[mf][j], SCI_H2);
            }
            #pragma unroll
            for (int nb = 0; nb < 2; nb++) {
                uint32_t rb = base + ((wn*32 + nb*16 + lr) * GLD + lh*8) * 2;
                ldm_x4(b0[nb], rb + T_B0*2);
                ldm_x4(b1[nb], rb + T_B1*2);
            }
            #pragma unroll
            for (int mf = 0; mf < 4; mf++)
                #pragma unroll
                for (int nb = 0; nb < 2; nb++)
                    #pragma unroll
                    for (int sub = 0; sub < 2; sub++) {
                        float* c = acc[mf][nb*2 + sub];
                        mma_fp16(c, a0[mf], b0[nb][sub], b0[nb][sub+2]);
                        mma_fp16(c, a1[mf], b1[nb][sub], b1[nb][sub+2]);
                    }
            if (s + 3 < 128) { load_stage(s + 3, (s + 3) & 3); CP_COMMIT(); }
        }
    }
};

// ---- fused Q/K/V projection: grid (16, 32, 3), z: 0=Q 1=K 2=V ---------------------
__global__ void __launch_bounds__(256, 2)
qkv_mma(const float* __restrict__ bq, const float* __restrict__ bk,
        const float* __restrict__ bv)
{
    extern __shared__ __half smem[];
    const int m0 = blockIdx.y * 128;
    const int n0 = blockIdx.x * 128;
    const int z  = blockIdx.z;

    GemmCore core;
    core.init(smem_u32(smem), m0, n0, g_xf, g_wfh[z], g_wfl[z]);

    float acc[4][4][4];
    #pragma unroll
    for (int i = 0; i < 4; i++)
        #pragma unroll
        for (int j = 0; j < 4; j++)
            #pragma unroll
            for (int k = 0; k < 4; k++) acc[i][j][k] = 0.f;

    core.run(acc);

    const float* bias = (z == 0) ? bq : (z == 1) ? bk : bv;
    const int g = core.lane >> 2, t = core.lane & 3;
    #pragma unroll
    for (int mf = 0; mf < 4; mf++) {
        const int r0 = m0 + core.wm*64 + mf*16 + g;
        const int r1 = r0 + 8;
        const int bb0 = r0 >> 11, pos0 = r0 & 2047;
        const int bb1 = r1 >> 11, pos1 = r1 & 2047;
        #pragma unroll
        for (int nf = 0; nf < 4; nf++) {
            const int col = n0 + core.wn*32 + nf*8 + 2*t;
            float b0 = bias[col], b1 = bias[col + 1];
            float v00 = acc[mf][nf][0] + b0, v01 = acc[mf][nf][1] + b1;
            float v10 = acc[mf][nf][2] + b0, v11 = acc[mf][nf][3] + b1;
            const int h = col >> 7, d = col & 127;
            size_t base0 = (((size_t)(bb0*NHEADS + h) * SEQLEN + pos0) * DHEAD + d);
            size_t base1 = (((size_t)(bb1*NHEADS + h) * SEQLEN + pos1) * DHEAD + d);
            if (z == 2) {
                __half h00 = __float2half(v00), h01 = __float2half(v01);
                __half h10 = __float2half(v10), h11 = __float2half(v11);
                __half2 hp0; hp0.x = h00; hp0.y = h01;
                __half2 hp1; hp1.x = h10; hp1.y = h11;
                *(__half2*)(g_vhf + base0) = hp0;
                *(__half2*)(g_vhf + base1) = hp1;
                __half2 lp0, lp1;
                lp0.x = __float2half((v00 - __half2float(h00)) * SPLIT_SC);
                lp0.y = __float2half((v01 - __half2float(h01)) * SPLIT_SC);
                lp1.x = __float2half((v10 - __half2float(h10)) * SPLIT_SC);
                lp1.y = __float2half((v11 - __half2float(h11)) * SPLIT_SC);
                *(__half2*)(g_vlf + base0) = lp0;
                *(__half2*)(g_vlf + base1) = lp1;
            } else {
                const int p = (col & 127) >> 1;
                float cs0 = g_cos[pos0*64 + p], sn0 = g_sin[pos0*64 + p];
                float cs1 = g_cos[pos1*64 + p], sn1 = g_sin[pos1*64 + p];
                const float sc = (z == 0) ? QK_SCALE : 1.0f;
                float x1 = v00, x2 = v01;
                v00 = (x1*cs0 - x2*sn0) * sc;  v01 = (x1*sn0 + x2*cs0) * sc;
                x1 = v10; x2 = v11;
                v10 = (x1*cs1 - x2*sn1) * sc;  v11 = (x1*sn1 + x2*cs1) * sc;
                if (z == 0) {
                    *(__half2*)(g_qf + base0) = __floats2half2_rn(v00, v01);
                    *(__half2*)(g_qf + base1) = __floats2half2_rn(v10, v11);
                } else {
                    __half h00 = __float2half(v00), h01 = __float2half(v01);
                    __half h10 = __float2half(v10), h11 = __float2half(v11);
                    __half2 hp0; hp0.x = h00; hp0.y = h01;
                    __half2 hp1; hp1.x = h10; hp1.y = h11;
                    *(__half2*)(g_kf + base0) = hp0;
                    *(__half2*)(g_kf + base1) = hp1;
                    __half2 lp0, lp1;
                    lp0.x = __float2half((v00 - __half2float(h00)) * SPLIT_SC);
                    lp0.y = __float2half((v01 - __half2float(h01)) * SPLIT_SC);
                    lp1.x = __float2half((v10 - __half2float(h10)) * SPLIT_SC);
                    lp1.y = __float2half((v11 - __half2float(h11)) * SPLIT_SC);
                    *(__half2*)(g_kr + base0) = lp0;
                    *(__half2*)(g_kr + base1) = lp1;
                }
            }
        }
    }
}

// ---- output projection -------------------------------------------------------------
__global__ void __launch_bounds__(256, 2)
out_mma(const float* __restrict__ bias, float* __restrict__ outp)
{
    extern __shared__ __half smem[];
    const int m0 = blockIdx.y * 128;
    const int n0 = blockIdx.x * 128;

    GemmCore core;
    core.init(smem_u32(smem), m0, n0, g_af, g_wfh[3], g_wfl[3]);

    float acc[4][4][4];
    #pragma unroll
    for (int i = 0; i < 4; i++)
        #pragma unroll
        for (int j = 0; j < 4; j++)
            #pragma unroll
            for (int k = 0; k < 4; k++) acc[i][j][k] = 0.f;

    core.run(acc);

    const int g = core.lane >> 2, t = core.lane & 3;
    #pragma unroll
    for (int mf = 0; mf < 4; mf++) {
        const int r0 = m0 + core.wm*64 + mf*16 + g;
        const int r1 = r0 + 8;
        #pragma unroll
        for (int nf = 0; nf < 4; nf++) {
            const int col = n0 + core.wn*32 + nf*8 + 2*t;
            float b0 = bias[col], b1 = bias[col + 1];
            *(float2*)(outp + (size_t)r0 * 2048 + col) =
                make_float2(acc[mf][nf][0] + b0, acc[mf][nf][1] + b1);
            *(float2*)(outp + (size_t)r1 * 2048 + col) =
                make_float2(acc[mf][nf][2] + b0, acc[mf][nf][3] + b1);
        }
    }
}

// ---------------- flash attention: 2-term fp16, A1-from-regs, occ 2 ----------------
#define AKVLD 136
#define A_SUB 8704
#define A_KH(b) ((b)*2*A_SUB)
#define A_KL(b) ((b)*2*A_SUB + A_SUB)
#define A_VH   (4*A_SUB)
#define A_VL   (5*A_SUB)
#define SM_ATTN_BYTES (6*A_SUB*2)        // 104448 B

__global__ void __launch_bounds__(128, 2)
attn_mma()
{
    extern __shared__ __half smn[];
    const uint32_t sb = smem_u32(smn);
    const int tid = threadIdx.x, lane = tid & 31, w = tid >> 5;
    const int bh = blockIdx.y;
    const int qt = 31 - blockIdx.x;
    const int q0 = qt * 64;

    const size_t qoff = ((size_t)bh * SEQLEN + q0) * DHEAD;
    for (int idx = tid; idx < 1024; idx += 128) {
        int row = idx >> 4, c = idx & 15;
        uint32_t off = (uint32_t)(row * AKVLD + c * 8) * 2;
        cp16(sb + A_KH(0)*2 + off, g_qf + qoff + row * 128 + c * 8);
    }
    CP_COMMIT(); CP_WAIT(0);
    __syncthreads();

    uint32_t qf[8][4], qs[8][4];
    const int lr = lane & 15, lhb = lane >> 4;
    #pragma unroll
    for (int kk = 0; kk < 8; kk++) {
        uint32_t ra = sb + (uint32_t)((w*16 + lr) * AKVLD + kk*16 + lhb*8) * 2;
        ldm_x4(qf[kk], ra + A_KH(0)*2);
        #pragma unroll
        for (int j = 0; j < 4; j++) qs[kk][j] = h2scale(qf[kk][j], SCI_H2);
    }
    __syncthreads();

    auto load_K = [&](int jt, int buf) {
        const size_t koff = ((size_t)bh * SEQLEN + jt * 64) * DHEAD;
        for (int idx = tid; idx < 1024; idx += 128) {
            int row = idx >> 4, c = idx & 15;
            uint32_t off = (uint32_t)(row * AKVLD + c * 8) * 2;
            int so = row * 128 + c * 8;
            cp16(sb + A_KH(buf)*2 + off, g_kf + koff + so);
            cp16(sb + A_KL(buf)*2 + off, g_kr + koff + so);
        }
    };
    auto load_V = [&](int jt) {
        const size_t koff = ((size_t)bh * SEQLEN + jt * 64) * DHEAD;
        for (int idx = tid; idx < 1024; idx += 128) {
            int row = idx >> 4, c = idx & 15;
            uint32_t off = (uint32_t)(row * AKVLD + c * 8) * 2;
            int so = row * 128 + c * 8;
            cp16(sb + A_VH*2 + off, g_vhf + koff + so);
            cp16(sb + A_VL*2 + off, g_vlf + koff + so);
        }
    };

    float m_[2] = {-INFINITY, -INFINITY};
    float l_[2] = {0.f, 0.f};
    float o[16][4];
    #pragma unroll
    for (int i = 0; i < 16; i++)
        #pragma unroll
        for (int j = 0; j < 4; j++) o[i][j] = 0.f;

    const int g  = lane >> 2, t2 = (lane & 3) * 2;
    const int wrow0 = q0 + w * 16;
    const int row0  = wrow0 + g;

    const int ntiles = qt + 1;
    load_K(0, 0); CP_COMMIT();
    load_V(0);    CP_COMMIT();

    for (int jt = 0; jt < ntiles; jt++) {
        const int kbuf = jt & 1;
        const int kv0 = jt * 64;
        const bool more = (jt + 1 < ntiles);

        if (more) { load_K(jt + 1, kbuf ^ 1); CP_COMMIT(); }
        if (more) CP_WAIT(2); else CP_WAIT(1);
        __syncthreads();

        const uint32_t kb = sb + A_KH(kbuf) * 2;

        float s[8][4];
        #pragma unroll
        for (int i = 0; i < 8; i++)
            #pragma unroll
            for (int j = 0; j < 4; j++) s[i][j] = 0.f;

        #pragma unroll
        for (int kk = 0; kk < 8; kk++) {
            #pragma unroll
            for (int nb = 0; nb < 4; nb++) {
                uint32_t kf4[4], kr4[4];
                uint32_t rb = kb + (uint32_t)((nb*16 + lr) * AKVLD + kk*16 + lhb*8) * 2;
                ldm_x4(kf4, rb);
                ldm_x4(kr4, rb + A_SUB*2);
                #pragma unroll
                for (int sub = 0; sub < 2; sub++) {
                    float* c = s[nb*2 + sub];
                    mma_fp16(c, qf[kk], kf4[sub], kf4[sub+2]);
                    mma_fp16(c, qs[kk], kr4[sub], kr4[sub+2]);
                }
            }
        }

        if (kv0 + 63 > wrow0) {
            #pragma unroll
            for (int nf = 0; nf < 8; nf++) {
                int c0 = kv0 + nf*8 + t2;
                if (c0     > row0)     s[nf][0] = -1e30f;
                if (c0 + 1 > row0)     s[nf][1] = -1e30f;
                if (c0     > row0 + 8) s[nf][2] = -1e30f;
                if (c0 + 1 > row0 + 8) s[nf][3] = -1e30f;
            }
        }

        float mx0 = -INFINITY, mx1 = -INFINITY;
        #pragma unroll
        for (int nf = 0; nf < 8; nf++) {
            mx0 = fmaxf(mx0, fmaxf(s[nf][0], s[nf][1]));
            mx1 = fmaxf(mx1, fmaxf(s[nf][2], s[nf][3]));
        }
        mx0 = fmaxf(mx0, __shfl_xor_sync(0xffffffffu, mx0, 1));
        mx0 = fmaxf(mx0, __shfl_xor_sync(0xffffffffu, mx0, 2));
        mx1 = fmaxf(mx1, __shfl_xor_sync(0xffffffffu, mx1, 1));
        mx1 = fmaxf(mx1, __shfl_xor_sync(0xffffffffu, mx1, 2));
        float mn0 = fmaxf(m_[0], mx0), mn1 = fmaxf(m_[1], mx1);
        float f0 = __expf(m_[0] - mn0), f1 = __expf(m_[1] - mn1);
        m_[0] = mn0; m_[1] = mn1;

        float sum0 = 0.f, sum1 = 0.f;
        #pragma unroll
        for (int nf = 0; nf < 8; nf++) {
            s[nf][0] = __expf(s[nf][0] - mn0); sum0 += s[nf][0];
            s[nf][1] = __expf(s[nf][1] - mn0); sum0 += s[nf][1];
            s[nf][2] = __expf(s[nf][2] - mn1); sum1 += s[nf][2];
            s[nf][3] = __expf(s[nf][3] - mn1); sum1 += s[nf][3];
        }
        sum0 += __shfl_xor_sync(0xffffffffu, sum0, 1);
        sum0 += __shfl_xor_sync(0xffffffffu, sum0, 2);
        sum1 += __shfl_xor_sync(0xffffffffu, sum1, 1);
        sum1 += __shfl_xor_sync(0xffffffffu, sum1, 2);
        l_[0] = l_[0] * f0 + sum0;
        l_[1] = l_[1] * f1 + sum1;

        #pragma unroll
        for (int nf = 0; nf < 16; nf++) {
            o[nf][0] *= f0; o[nf][1] *= f0;
            o[nf][2] *= f1; o[nf][3] *= f1;
        }

        uint32_t pf[4][4], ps[4][4];
        #pragma unroll
        for (int kf2 = 0; kf2 < 4; kf2++) {
            #pragma unroll
            for (int j = 0; j < 4; j++) {
                int nf = 2*kf2 + (j >> 1);
                int c0 = (j & 1) * 2;
                pf[kf2][j] = packh2(s[nf][c0], s[nf][c0 + 1]);
                ps[kf2][j] = h2scale(pf[kf2][j], SCI_H2);
            }
        }

        if (more) CP_WAIT(1); else CP_WAIT(0);
        __syncthreads();

        const uint32_t vbase = sb + A_VH * 2;
        const int matv = lane >> 3, jv = lane & 7;
        #pragma unroll
        for (int kf2 = 0; kf2 < 4; kf2++) {
            #pragma unroll
            for (int ng = 0; ng < 8; ng++) {
                uint32_t vh4[4], vl4[4];
                uint32_t va = vbase + (uint32_t)((kf2*16 + jv + ((matv & 1) << 3)) * AKVLD
                                                + ng*16 + ((matv >> 1) << 3)) * 2;
                ldm_x4_t(vh4, va);
                ldm_x4_t(vl4, va + A_SUB*2);
                #pragma unroll
                for (int sub = 0; sub < 2; sub++) {
                    float* c = o[ng*2 + sub];
                    mma_fp16(c, pf[kf2], vh4[sub*2], vh4[sub*2+1]);
                    mma_fp16(c, ps[kf2], vl4[sub*2], vl4[sub*2+1]);
                }
            }
        }
        __syncthreads();
        if (more) { load_V(jt + 1); CP_COMMIT(); }
    }

    const float inv0 = 1.f / l_[0];
    const float inv1 = 1.f / l_[1];
    const int bb = bh >> 4, h = bh & 15;
    const size_t rA0 = (size_t)(bb * SEQLEN + row0) * D_MODEL + h * DHEAD;
    const size_t rA1 = rA0 + 8 * D_MODEL;
    #pragma unroll
    for (int nf = 0; nf < 16; nf++) {
        int d = nf*8 + t2;
        *(__half2*)(g_af + rA0 + d) = __floats2half2_rn(o[nf][0]*inv0, o[nf][1]*inv0);
        *(__half2*)(g_af + rA1 + d) = __floats2half2_rn(o[nf][2]*inv1, o[nf][3]*inv1);
    }
}

// ---------------- launch -----------------------------------------------------------
extern "C" void kernel_launch(void* const* d_in, const int* in_sizes, int n_in,
                              void* d_out, int out_size)
{
    const float* x  = (const float*)d_in[0];
    const float* Wq = (const float*)d_in[1];
    const float* bq = (const float*)d_in[2];
    const float* Wk = (const float*)d_in[3];
    const float* bk = (const float*)d_in[4];
    const float* Wv = (const float*)d_in[5];
    const float* bv = (const float*)d_in[6];
    const float* Wo = (const float*)d_in[7];
    const float* bo = (const float*)d_in[8];
    float* out = (float*)d_out;

    cudaFuncSetAttribute(attn_mma, cudaFuncAttributeMaxDynamicSharedMemorySize, SM_ATTN_BYTES);
    cudaFuncSetAttribute(qkv_mma,  cudaFuncAttributeMaxDynamicSharedMemorySize, SMEM_GEMM_BYTES);
    cudaFuncSetAttribute(out_mma,  cudaFuncAttributeMaxDynamicSharedMemorySize, SMEM_GEMM_BYTES);

    rope_table_kernel<<<512, 256>>>();

    const int NX = MROWS * D_MODEL;
    const int NW = D_MODEL * D_MODEL;
    split_x_kernel<<<NX/256, 256>>>(x);
    split_w_kernel<<<dim3(NW/256, 4), 256>>>(Wq, Wk, Wv, Wo);

    qkv_mma<<<dim3(16, 32, 3), 256, SMEM_GEMM_BYTES>>>(bq, bk, bv);

    attn_mma<<<dim3(32, 32), 128, SM_ATTN_BYTES>>>();

    out_mma<<<dim3(16, 32), 256, SMEM_GEMM_BYTES>>>(bo, out);
}

// round 15
// speedup vs baseline: 1.3721x; 1.3721x over previous
#include <cuda_runtime.h>
#include <cuda_fp16.h>
#include <math.h>
#include <stdint.h>

#define D_MODEL 2048
#define NHEADS  16
#define DHEAD   128
#define SEQLEN  2048
#define BATCH   2
#define MROWS   (BATCH*SEQLEN)   // 4096
#define QK_SCALE 0.08838834764831845f   // 1/sqrt(128)
#define SPLIT_SC 2048.0f
#define SPLIT_SCI (1.0f/2048.0f)

// ---------------- scratch (device globals) ------------------------------------------
__device__ float g_cos[SEQLEN*(DHEAD/2)];
__device__ float g_sin[SEQLEN*(DHEAD/2)];

__device__ __half g_xf[MROWS*D_MODEL];                // fp16(x)
__device__ __half g_wfh[4][D_MODEL*D_MODEL];          // 0=Wq 1=Wk 2=Wv 3=Wo
__device__ __half g_wfl[2][D_MODEL*D_MODEL];          // residual*2048 for Wq, Wk only
__device__ __half g_qf[BATCH*NHEADS*SEQLEN*DHEAD];    // fp16(q·scale)
__device__ __half g_kf[BATCH*NHEADS*SEQLEN*DHEAD];    // fp16(k)
__device__ __half g_kr[BATCH*NHEADS*SEQLEN*DHEAD];    // fp16((k-kf)*2048)
__device__ __half g_vhf[BATCH*NHEADS*SEQLEN*DHEAD];   // fp16(v)  (1-term)
__device__ __half g_af[MROWS*D_MODEL];                // fp16(attn out)

// ---------------- PTX helpers --------------------------------------------------------
__device__ __forceinline__ uint32_t smem_u32(const void* p) {
    uint32_t a;
    asm("{ .reg .u64 t; cvta.to.shared.u64 t, %1; cvt.u32.u64 %0, t; }" : "=r"(a) : "l"(p));
    return a;
}
__device__ __forceinline__ void cp16(uint32_t dst, const void* src) {
    asm volatile("cp.async.cg.shared.global [%0], [%1], 16;" :: "r"(dst), "l"(src));
}
#define CP_COMMIT() asm volatile("cp.async.commit_group;" ::: "memory")
#define CP_WAIT(n)  asm volatile("cp.async.wait_group %0;" :: "n"(n) : "memory")

__device__ __forceinline__ void ldm_x4(uint32_t* r, uint32_t addr) {
    asm volatile("ldmatrix.sync.aligned.m8n8.x4.shared.b16 {%0,%1,%2,%3}, [%4];"
                 : "=r"(r[0]), "=r"(r[1]), "=r"(r[2]), "=r"(r[3]) : "r"(addr));
}
__device__ __forceinline__ void ldm_x4_t(uint32_t* r, uint32_t addr) {
    asm volatile("ldmatrix.sync.aligned.m8n8.x4.trans.shared.b16 {%0,%1,%2,%3}, [%4];"
                 : "=r"(r[0]), "=r"(r[1]), "=r"(r[2]), "=r"(r[3]) : "r"(addr));
}
__device__ __forceinline__ void mma_fp16(float* c, const uint32_t* a, uint32_t b0, uint32_t b1) {
    asm volatile("mma.sync.aligned.m16n8k16.row.col.f32.f16.f16.f32 "
                 "{%0,%1,%2,%3}, {%4,%5,%6,%7}, {%8,%9}, {%0,%1,%2,%3};"
                 : "+f"(c[0]), "+f"(c[1]), "+f"(c[2]), "+f"(c[3])
                 : "r"(a[0]), "r"(a[1]), "r"(a[2]), "r"(a[3]), "r"(b0), "r"(b1));
}
__device__ __forceinline__ uint32_t packh2(float lo, float hi) {
    uint32_t r;
    asm("cvt.rn.f16x2.f32 %0, %1, %2;" : "=r"(r) : "f"(hi), "f"(lo));
    return r;
}
__device__ __forceinline__ uint32_t h2scale(uint32_t v, uint32_t sc2) {
    uint32_t r;
    asm("mul.rn.f16x2 %0, %1, %2;" : "=r"(r) : "r"(v), "r"(sc2));
    return r;
}
#define SCI_H2 0x10001000u   // fp16x2 {2^-11, 2^-11}

// ---------------- RoPE tables --------------------------------------------------------
__global__ void rope_table_kernel() {
    int idx = blockIdx.x * blockDim.x + threadIdx.x;
    int pos = idx >> 6;
    int p   = idx & 63;
    double freq = exp(-((double)(2 * p) / 128.0) * log(10000.0));
    double ang  = (double)pos * freq;
    g_cos[idx] = (float)cos(ang);
    g_sin[idx] = (float)sin(ang);
}

// ---------------- split kernels ------------------------------------------------------
__global__ void split_x_kernel(const float* __restrict__ src) {
    int i = blockIdx.x * 256 + threadIdx.x;
    g_xf[i] = __float2half(src[i]);
}
// y: 0=Wq(2t) 1=Wk(2t) 2=Wv(1t) 3=Wo(1t)
__global__ void split_w_kernel(const float* __restrict__ w0, const float* __restrict__ w1,
                               const float* __restrict__ w2, const float* __restrict__ w3) {
    int i = blockIdx.x * 256 + threadIdx.x;
    int wsel = blockIdx.y;
    const float* s = (wsel == 0) ? w0 : (wsel == 1) ? w1 : (wsel == 2) ? w2 : w3;
    float v = s[i];
    __half h = __float2half(v);
    g_wfh[wsel][i] = h;
    if (wsel < 2)
        g_wfl[wsel][i] = __float2half((v - __half2float(h)) * SPLIT_SC);
}

// ---------------- GEMM core (R13 geometry: 8 warps, 4m x 2n, warp tile 32x64) -------
// TERMS=2: acc = A*B0 + (A*2^-11)*B1 ;  TERMS=1: acc = A*B0
#define GLD 24
#define T_A0 0
#define T_B0 (128*GLD)
#define T_B1 (2*128*GLD)
#define STAGE_HALVES (3*128*GLD)              // 18432 B
#define SMEM_GEMM_BYTES (4*STAGE_HALVES*2)    // 73728 B

struct GemmCore {
    uint32_t sb;
    int lane, wm, wn, lrow, lc, lr, lh;
    const uint16_t *pA0, *pB0, *pB1;

    __device__ __forceinline__ void init(uint32_t sb_, int m0, int n0,
                                         const void* A0, const void* B0, const void* B1) {
        sb = sb_;
        int tid = threadIdx.x;
        lane = tid & 31;
        int warp = tid >> 5;
        wm = warp & 3; wn = warp >> 2;
        lrow = tid & 127; lc = tid >> 7;
        lr = lane & 15; lh = lane >> 4;
        pA0 = (const uint16_t*)A0 + (size_t)(m0 + lrow) * 2048;
        pB0 = (const uint16_t*)B0 + (size_t)(n0 + lrow) * 2048;
        pB1 = B1 ? (const uint16_t*)B1 + (size_t)(n0 + lrow) * 2048 : nullptr;
    }
    template<int TERMS>
    __device__ __forceinline__ void load_stage(int s, int buf) {
        const int ks = s * 16 + lc * 8;
        const uint32_t base = sb + buf * STAGE_HALVES * 2;
        const uint32_t off = (lrow * GLD + lc * 8) * 2;
        cp16(base + T_A0*2 + off, pA0 + ks);
        cp16(base + T_B0*2 + off, pB0 + ks);
        if (TERMS == 2) cp16(base + T_B1*2 + off, pB1 + ks);
    }
    template<int TERMS>
    __device__ __forceinline__ void run(float acc[2][8][4]) {
        load_stage<TERMS>(0, 0); CP_COMMIT();
        load_stage<TERMS>(1, 1); CP_COMMIT();
        load_stage<TERMS>(2, 2); CP_COMMIT();
        for (int s = 0; s < 128; s++) {
            const int rem = 127 - s;
            if      (rem >= 2) CP_WAIT(2);
            else if (rem == 1) CP_WAIT(1);
            else               CP_WAIT(0);
            __syncthreads();
            const uint32_t base = sb + (s & 3) * STAGE_HALVES * 2;
            uint32_t a0[2][4], a1[2][4], b0[4][4], b1[4][4];
            #pragma unroll
            for (int mf = 0; mf < 2; mf++) {
                uint32_t ra = base + ((wm*32 + mf*16 + lr) * GLD + lh*8) * 2;
                ldm_x4(a0[mf], ra + T_A0*2);
                if (TERMS == 2) {
                    #pragma unroll
                    for (int j = 0; j < 4; j++) a1[mf][j] = h2scale(a0[mf][j], SCI_H2);
                }
            }
            #pragma unroll
            for (int nb = 0; nb < 4; nb++) {
                uint32_t rb = base + ((wn*64 + nb*16 + lr) * GLD + lh*8) * 2;
                ldm_x4(b0[nb], rb + T_B0*2);
                if (TERMS == 2) ldm_x4(b1[nb], rb + T_B1*2);
            }
            #pragma unroll
            for (int mf = 0; mf < 2; mf++)
                #pragma unroll
                for (int nb = 0; nb < 4; nb++)
                    #pragma unroll
                    for (int sub = 0; sub < 2; sub++) {
                        float* c = acc[mf][nb*2 + sub];
                        mma_fp16(c, a0[mf], b0[nb][sub], b0[nb][sub+2]);
                        if (TERMS == 2) mma_fp16(c, a1[mf], b1[nb][sub], b1[nb][sub+2]);
                    }
            if (s + 3 < 128) { load_stage<TERMS>(s + 3, (s + 3) & 3); CP_COMMIT(); }
        }
    }
};

// ---- fused Q/K/V projection: grid (16, 32, 3), z: 0=Q(2t) 1=K(2t) 2=V(1t) ----------
__global__ void __launch_bounds__(256, 2)
qkv_mma(const float* __restrict__ bq, const float* __restrict__ bk,
        const float* __restrict__ bv)
{
    extern __shared__ __half smem[];
    const int m0 = blockIdx.y * 128;
    const int n0 = blockIdx.x * 128;
    const int z  = blockIdx.z;

    GemmCore core;
    float acc[2][8][4];
    #pragma unroll
    for (int i = 0; i < 2; i++)
        #pragma unroll
        for (int j = 0; j < 8; j++)
            #pragma unroll
            for (int k = 0; k < 4; k++) acc[i][j][k] = 0.f;

    if (z == 2) {
        core.init(smem_u32(smem), m0, n0, g_xf, g_wfh[2], nullptr);
        core.run<1>(acc);
    } else {
        core.init(smem_u32(smem), m0, n0, g_xf, g_wfh[z], g_wfl[z]);
        core.run<2>(acc);
    }

    const float* bias = (z == 0) ? bq : (z == 1) ? bk : bv;
    const int g = core.lane >> 2, t = core.lane & 3;
    #pragma unroll
    for (int mf = 0; mf < 2; mf++) {
        const int r0 = m0 + core.wm*32 + mf*16 + g;
        const int r1 = r0 + 8;
        const int bb0 = r0 >> 11, pos0 = r0 & 2047;
        const int bb1 = r1 >> 11, pos1 = r1 & 2047;
        #pragma unroll
        for (int nf = 0; nf < 8; nf++) {
            const int col = n0 + core.wn*64 + nf*8 + 2*t;
            float b0 = bias[col], b1 = bias[col + 1];
            float v00 = acc[mf][nf][0] + b0, v01 = acc[mf][nf][1] + b1;
            float v10 = acc[mf][nf][2] + b0, v11 = acc[mf][nf][3] + b1;
            const int h = col >> 7, d = col & 127;
            size_t base0 = (((size_t)(bb0*NHEADS + h) * SEQLEN + pos0) * DHEAD + d);
            size_t base1 = (((size_t)(bb1*NHEADS + h) * SEQLEN + pos1) * DHEAD + d);
            if (z == 2) {
                *(__half2*)(g_vhf + base0) = __floats2half2_rn(v00, v01);
                *(__half2*)(g_vhf + base1) = __floats2half2_rn(v10, v11);
            } else {
                const int p = (col & 127) >> 1;
                float cs0 = g_cos[pos0*64 + p], sn0 = g_sin[pos0*64 + p];
                float cs1 = g_cos[pos1*64 + p], sn1 = g_sin[pos1*64 + p];
                const float sc = (z == 0) ? QK_SCALE : 1.0f;
                float x1 = v00, x2 = v01;
                v00 = (x1*cs0 - x2*sn0) * sc;  v01 = (x1*sn0 + x2*cs0) * sc;
                x1 = v10; x2 = v11;
                v10 = (x1*cs1 - x2*sn1) * sc;  v11 = (x1*sn1 + x2*cs1) * sc;
                if (z == 0) {
                    *(__half2*)(g_qf + base0) = __floats2half2_rn(v00, v01);
                    *(__half2*)(g_qf + base1) = __floats2half2_rn(v10, v11);
                } else {
                    __half h00 = __float2half(v00), h01 = __float2half(v01);
                    __half h10 = __float2half(v10), h11 = __float2half(v11);
                    __half2 hp0; hp0.x = h00; hp0.y = h01;
                    __half2 hp1; hp1.x = h10; hp1.y = h11;
                    *(__half2*)(g_kf + base0) = hp0;
                    *(__half2*)(g_kf + base1) = hp1;
                    __half2 lp0, lp1;
                    lp0.x = __float2half((v00 - __half2float(h00)) * SPLIT_SC);
                    lp0.y = __float2half((v01 - __half2float(h01)) * SPLIT_SC);
                    lp1.x = __float2half((v10 - __half2float(h10)) * SPLIT_SC);
                    lp1.y = __float2half((v11 - __half2float(h11)) * SPLIT_SC);
                    *(__half2*)(g_kr + base0) = lp0;
                    *(__half2*)(g_kr + base1) = lp1;
                }
            }
        }
    }
}

// ---- output projection: 1-term fp16 -------------------------------------------------
__global__ void __launch_bounds__(256, 2)
out_mma(const float* __restrict__ bias, float* __restrict__ outp)
{
    extern __shared__ __half smem[];
    const int m0 = blockIdx.y * 128;
    const int n0 = blockIdx.x * 128;

    GemmCore core;
    core.init(smem_u32(smem), m0, n0, g_af, g_wfh[3], nullptr);

    float acc[2][8][4];
    #pragma unroll
    for (int i = 0; i < 2; i++)
        #pragma unroll
        for (int j = 0; j < 8; j++)
            #pragma unroll
            for (int k = 0; k < 4; k++) acc[i][j][k] = 0.f;

    core.run<1>(acc);

    const int g = core.lane >> 2, t = core.lane & 3;
    #pragma unroll
    for (int mf = 0; mf < 2; mf++) {
        const int r0 = m0 + core.wm*32 + mf*16 + g;
        const int r1 = r0 + 8;
        #pragma unroll
        for (int nf = 0; nf < 8; nf++) {
            const int col = n0 + core.wn*64 + nf*8 + 2*t;
            float b0 = bias[col], b1 = bias[col + 1];
            *(float2*)(outp + (size_t)r0 * 2048 + col) =
                make_float2(acc[mf][nf][0] + b0, acc[mf][nf][1] + b1);
            *(float2*)(outp + (size_t)r1 * 2048 + col) =
                make_float2(acc[mf][nf][2] + b0, acc[mf][nf][3] + b1);
        }
    }
}

// ---------------- flash attention: S 2-term, PV 1-term, occ 2 ----------------------
#define AKVLD 136
#define A_SUB 8704
#define A_KH(b) ((b)*2*A_SUB)
#define A_KL(b) ((b)*2*A_SUB + A_SUB)
#define A_VH   (4*A_SUB)
#define SM_ATTN_BYTES (5*A_SUB*2)        // 87040 B (occ 2 easily)

__global__ void __launch_bounds__(128, 2)
attn_mma()
{
    extern __shared__ __half smn[];
    const uint32_t sb = smem_u32(smn);
    const int tid = threadIdx.x, lane = tid & 31, w = tid >> 5;
    const int bh = blockIdx.y;
    const int qt = 31 - blockIdx.x;
    const int q0 = qt * 64;

    const size_t qoff = ((size_t)bh * SEQLEN + q0) * DHEAD;
    for (int idx = tid; idx < 1024; idx += 128) {
        int row = idx >> 4, c = idx & 15;
        uint32_t off = (uint32_t)(row * AKVLD + c * 8) * 2;
        cp16(sb + A_KH(0)*2 + off, g_qf + qoff + row * 128 + c * 8);
    }
    CP_COMMIT(); CP_WAIT(0);
    __syncthreads();

    uint32_t qf[8][4], qs[8][4];
    const int lr = lane & 15, lhb = lane >> 4;
    #pragma unroll
    for (int kk = 0; kk < 8; kk++) {
        uint32_t ra = sb + (uint32_t)((w*16 + lr) * AKVLD + kk*16 + lhb*8) * 2;
        ldm_x4(qf[kk], ra + A_KH(0)*2);
        #pragma unroll
        for (int j = 0; j < 4; j++) qs[kk][j] = h2scale(qf[kk][j], SCI_H2);
    }
    __syncthreads();

    auto load_K = [&](int jt, int buf) {
        const size_t koff = ((size_t)bh * SEQLEN + jt * 64) * DHEAD;
        for (int idx = tid; idx < 1024; idx += 128) {
            int row = idx >> 4, c = idx & 15;
            uint32_t off = (uint32_t)(row * AKVLD + c * 8) * 2;
            int so = row * 128 + c * 8;
            cp16(sb + A_KH(buf)*2 + off, g_kf + koff + so);
            cp16(sb + A_KL(buf)*2 + off, g_kr + koff + so);
        }
    };
    auto load_V = [&](int jt) {
        const size_t koff = ((size_t)bh * SEQLEN + jt * 64) * DHEAD;
        for (int idx = tid; idx < 1024; idx += 128) {
            int row = idx >> 4, c = idx & 15;
            uint32_t off = (uint32_t)(row * AKVLD + c * 8) * 2;
            cp16(sb + A_VH*2 + off, g_vhf + koff + row * 128 + c * 8);
        }
    };

    float m_[2] = {-INFINITY, -INFINITY};
    float l_[2] = {0.f, 0.f};
    float o[16][4];
    #pragma unroll
    for (int i = 0; i < 16; i++)
        #pragma unroll
        for (int j = 0; j < 4; j++) o[i][j] = 0.f;

    const int g  = lane >> 2, t2 = (lane & 3) * 2;
    const int wrow0 = q0 + w * 16;
    const int row0  = wrow0 + g;

    const int ntiles = qt + 1;
    load_K(0, 0); CP_COMMIT();
    load_V(0);    CP_COMMIT();

    for (int jt = 0; jt < ntiles; jt++) {
        const int kbuf = jt & 1;
        const int kv0 = jt * 64;
        const bool more = (jt + 1 < ntiles);

        if (more) { load_K(jt + 1, kbuf ^ 1); CP_COMMIT(); }
        if (more) CP_WAIT(2); else CP_WAIT(1);
        __syncthreads();

        const uint32_t kb = sb + A_KH(kbuf) * 2;

        // ---- S = Q K^T (2-term: qf*Kf + qs*Kr) ----
        float s[8][4];
        #pragma unroll
        for (int i = 0; i < 8; i++)
            #pragma unroll
            for (int j = 0; j < 4; j++) s[i][j] = 0.f;

        #pragma unroll
        for (int kk = 0; kk < 8; kk++) {
            #pragma unroll
            for (int nb = 0; nb < 4; nb++) {
                uint32_t kf4[4], kr4[4];
                uint32_t rb = kb + (uint32_t)((nb*16 + lr) * AKVLD + kk*16 + lhb*8) * 2;
                ldm_x4(kf4, rb);
                ldm_x4(kr4, rb + A_SUB*2);
                #pragma unroll
                for (int sub = 0; sub < 2; sub++) {
                    float* c = s[nb*2 + sub];
                    mma_fp16(c, qf[kk], kf4[sub], kf4[sub+2]);
                    mma_fp16(c, qs[kk], kr4[sub], kr4[sub+2]);
                }
            }
        }

        if (kv0 + 63 > wrow0) {
            #pragma unroll
            for (int nf = 0; nf < 8; nf++) {
                int c0 = kv0 + nf*8 + t2;
                if (c0     > row0)     s[nf][0] = -1e30f;
                if (c0 + 1 > row0)     s[nf][1] = -1e30f;
                if (c0     > row0 + 8) s[nf][2] = -1e30f;
                if (c0 + 1 > row0 + 8) s[nf][3] = -1e30f;
            }
        }

        float mx0 = -INFINITY, mx1 = -INFINITY;
        #pragma unroll
        for (int nf = 0; nf < 8; nf++) {
            mx0 = fmaxf(mx0, fmaxf(s[nf][0], s[nf][1]));
            mx1 = fmaxf(mx1, fmaxf(s[nf][2], s[nf][3]));
        }
        mx0 = fmaxf(mx0, __shfl_xor_sync(0xffffffffu, mx0, 1));
        mx0 = fmaxf(mx0, __shfl_xor_sync(0xffffffffu, mx0, 2));
        mx1 = fmaxf(mx1, __shfl_xor_sync(0xffffffffu, mx1, 1));
        mx1 = fmaxf(mx1, __shfl_xor_sync(0xffffffffu, mx1, 2));
        float mn0 = fmaxf(m_[0], mx0), mn1 = fmaxf(m_[1], mx1);
        float f0 = __expf(m_[0] - mn0), f1 = __expf(m_[1] - mn1);
        m_[0] = mn0; m_[1] = mn1;

        float sum0 = 0.f, sum1 = 0.f;
        #pragma unroll
        for (int nf = 0; nf < 8; nf++) {
            s[nf][0] = __expf(s[nf][0] - mn0); sum0 += s[nf][0];
            s[nf][1] = __expf(s[nf][1] - mn0); sum0 += s[nf][1];
            s[nf][2] = __expf(s[nf][2] - mn1); sum1 += s[nf][2];
            s[nf][3] = __expf(s[nf][3] - mn1); sum1 += s[nf][3];
        }
        sum0 += __shfl_xor_sync(0xffffffffu, sum0, 1);
        sum0 += __shfl_xor_sync(0xffffffffu, sum0, 2);
        sum1 += __shfl_xor_sync(0xffffffffu, sum1, 1);
        sum1 += __shfl_xor_sync(0xffffffffu, sum1, 2);
        l_[0] = l_[0] * f0 + sum0;
        l_[1] = l_[1] * f1 + sum1;

        #pragma unroll
        for (int nf = 0; nf < 16; nf++) {
            o[nf][0] *= f0; o[nf][1] *= f0;
            o[nf][2] *= f1; o[nf][3] *= f1;
        }

        // ---- pack P as A-frags (1-term) ----
        uint32_t pf[4][4];
        #pragma unroll
        for (int kf2 = 0; kf2 < 4; kf2++) {
            #pragma unroll
            for (int j = 0; j < 4; j++) {
                int nf = 2*kf2 + (j >> 1);
                int c0 = (j & 1) * 2;
                pf[kf2][j] = packh2(s[nf][c0], s[nf][c0 + 1]);
            }
        }

        if (more) CP_WAIT(1); else CP_WAIT(0);
        __syncthreads();

        // ---- O += P V (1-term fp16) ----
        const uint32_t vbase = sb + A_VH * 2;
        const int matv = lane >> 3, jv = lane & 7;
        #pragma unroll
        for (int kf2 = 0; kf2 < 4; kf2++) {
            #pragma unroll
            for (int ng = 0; ng < 8; ng++) {
                uint32_t vh4[4];
                uint32_t va = vbase + (uint32_t)((kf2*16 + jv + ((matv & 1) << 3)) * AKVLD
                                                + ng*16 + ((matv >> 1) << 3)) * 2;
                ldm_x4_t(vh4, va);
                #pragma unroll
                for (int sub = 0; sub < 2; sub++)
                    mma_fp16(o[ng*2 + sub], pf[kf2], vh4[sub*2], vh4[sub*2+1]);
            }
        }
        __syncthreads();
        if (more) { load_V(jt + 1); CP_COMMIT(); }
    }

    const float inv0 = 1.f / l_[0];
    const float inv1 = 1.f / l_[1];
    const int bb = bh >> 4, h = bh & 15;
    const size_t rA0 = (size_t)(bb * SEQLEN + row0) * D_MODEL + h * DHEAD;
    const size_t rA1 = rA0 + 8 * D_MODEL;
    #pragma unroll
    for (int nf = 0; nf < 16; nf++) {
        int d = nf*8 + t2;
        *(__half2*)(g_af + rA0 + d) = __floats2half2_rn(o[nf][0]*inv0, o[nf][1]*inv0);
        *(__half2*)(g_af + rA1 + d) = __floats2half2_rn(o[nf][2]*inv1, o[nf][3]*inv1);
    }
}

// ---------------- launch -------------------------------------------------------------
extern "C" void kernel_launch(void* const* d_in, const int* in_sizes, int n_in,
                              void* d_out, int out_size)
{
    const float* x  = (const float*)d_in[0];
    const float* Wq = (const float*)d_in[1];
    const float* bq = (const float*)d_in[2];
    const float* Wk = (const float*)d_in[3];
    const float* bk = (const float*)d_in[4];
    const float* Wv = (const float*)d_in[5];
    const float* bv = (const float*)d_in[6];
    const float* Wo = (const float*)d_in[7];
    const float* bo = (const float*)d_in[8];
    float* out = (float*)d_out;

    cudaFuncSetAttribute(attn_mma, cudaFuncAttributeMaxDynamicSharedMemorySize, SM_ATTN_BYTES);
    cudaFuncSetAttribute(qkv_mma,  cudaFuncAttributeMaxDynamicSharedMemorySize, SMEM_GEMM_BYTES);
    cudaFuncSetAttribute(out_mma,  cudaFuncAttributeMaxDynamicSharedMemorySize, SMEM_GEMM_BYTES);

    rope_table_kernel<<<512, 256>>>();

    const int NX = MROWS * D_MODEL;
    const int NW = D_MODEL * D_MODEL;
    split_x_kernel<<<NX/256, 256>>>(x);
    split_w_kernel<<<dim3(NW/256, 4), 256>>>(Wq, Wk, Wv, Wo);

    qkv_mma<<<dim3(16, 32, 3), 256, SMEM_GEMM_BYTES>>>(bq, bk, bv);

    attn_mma<<<dim3(32, 32), 128, SM_ATTN_BYTES>>>();

    out_mma<<<dim3(16, 32), 256, SMEM_GEMM_BYTES>>>(bo, out);
}